// round 1
// baseline (speedup 1.0000x reference)
#include <cuda_runtime.h>

#define NN 50000
#define EE 800000
#define HID 64

// Scratch (allocation-free rule: __device__ globals)
__device__ float g_h[NN * HID];     // GEMM output (pre-aggregation features)
__device__ float g_act[NN * HID];   // layer-1 activations
__device__ int   g_cnt[NN];         // in-degree histogram (dst-based, excl. self-loop)
__device__ int   g_off[NN + 1];     // CSR row offsets
__device__ int   g_cur[NN];         // fill cursors
__device__ float g_dinv[NN];        // rsqrt(deg) per node (deg includes self-loop)
__device__ int   g_csrc[EE];        // CSR: source node per edge (grouped by dst)
__device__ float g_cnorm[EE];       // CSR: dinv[src]*dinv[dst] per edge

__global__ void k_zero() {
    int i = blockIdx.x * blockDim.x + threadIdx.x;
    if (i < NN) { g_cnt[i] = 0; g_cur[i] = 0; }
}

__global__ void k_hist(const int* __restrict__ dst) {
    int e = blockIdx.x * blockDim.x + threadIdx.x;
    if (e < EE) atomicAdd(&g_cnt[dst[e]], 1);
}

// Single-block exclusive scan over 50000 counts + dinv computation.
__global__ void k_scan() {
    __shared__ int sm[1024];
    int t = threadIdx.x;
    const int C = (NN + 1023) / 1024;   // 49
    int start = t * C;
    int end = start + C;
    if (end > NN) end = NN;
    int sum = 0;
    for (int i = start; i < end; i++) sum += g_cnt[i];
    sm[t] = sum;
    __syncthreads();
    for (int ofs = 1; ofs < 1024; ofs <<= 1) {
        int v = (t >= ofs) ? sm[t - ofs] : 0;
        __syncthreads();
        sm[t] += v;
        __syncthreads();
    }
    int base = sm[t] - sum;  // exclusive prefix
    for (int i = start; i < end; i++) {
        int c = g_cnt[i];
        g_off[i] = base;
        base += c;
        g_dinv[i] = rsqrtf((float)(c + 1));  // +1 self-loop => deg > 0 always
    }
    if (t == 0) g_off[NN] = EE;
}

__global__ void k_fill(const int* __restrict__ src, const int* __restrict__ dst) {
    int e = blockIdx.x * blockDim.x + threadIdx.x;
    if (e >= EE) return;
    int s = src[e], d = dst[e];
    int pos = g_off[d] + atomicAdd(&g_cur[d], 1);
    g_csrc[pos] = s;
    g_cnorm[pos] = g_dinv[s] * g_dinv[d];
}

// fp32 GEMM: OUT[n,64] = X[n,Kdim] @ W[Kdim,64]
// Block = 128 threads (16 x 8); tile 128 rows x 64 cols; micro-tile 16x4 per thread.
__global__ __launch_bounds__(128, 4) void k_gemm(
    const float* __restrict__ X, const float* __restrict__ W,
    float* __restrict__ OUT, int n, int Kdim) {
    __shared__ float Xs[128][33];   // +1 pad: rows 8 apart land on distinct banks
    __shared__ float Ws[32][HID];
    int tid = threadIdx.x;
    int tx = tid & 15;      // 16 col-groups of 4
    int ty = tid >> 4;      // 8 row-groups of 16
    int r0 = blockIdx.x * 128;

    float4 acc[16];
#pragma unroll
    for (int r = 0; r < 16; r++) acc[r] = make_float4(0.f, 0.f, 0.f, 0.f);

    for (int k0 = 0; k0 < Kdim; k0 += 32) {
        // X tile: 128 rows x 32 k (coalesced float4 loads)
#pragma unroll
        for (int j = 0; j < 8; j++) {
            int idx = tid + j * 128;
            int row = idx >> 3;
            int c4 = (idx & 7) * 4;
            float4 v = make_float4(0.f, 0.f, 0.f, 0.f);
            int gr = r0 + row;
            if (gr < n) v = *(const float4*)(X + (size_t)gr * Kdim + k0 + c4);
            Xs[row][c4] = v.x; Xs[row][c4 + 1] = v.y;
            Xs[row][c4 + 2] = v.z; Xs[row][c4 + 3] = v.w;
        }
        // W tile: 32 k x 64 cols
#pragma unroll
        for (int j = 0; j < 4; j++) {
            int idx = tid + j * 128;
            int row = idx >> 4;
            int c4 = (idx & 15) * 4;
            *(float4*)(&Ws[row][c4]) =
                *(const float4*)(W + (size_t)(k0 + row) * HID + c4);
        }
        __syncthreads();
#pragma unroll
        for (int kk = 0; kk < 32; kk++) {
            float4 wv = *(const float4*)(&Ws[kk][tx * 4]);
#pragma unroll
            for (int r = 0; r < 16; r++) {
                float xv = Xs[ty * 16 + r][kk];
                acc[r].x += xv * wv.x;
                acc[r].y += xv * wv.y;
                acc[r].z += xv * wv.z;
                acc[r].w += xv * wv.w;
            }
        }
        __syncthreads();
    }
#pragma unroll
    for (int r = 0; r < 16; r++) {
        int gr = r0 + ty * 16 + r;
        if (gr < n) *(float4*)(OUT + (size_t)gr * HID + tx * 4) = acc[r];
    }
}

// Gather aggregation: 8 threads per node, each owns 8 of the 64 features.
// out[i] = [relu]( sum_{e: dst=i} H[src_e]*norm_e + dinv[i]^2*H[i] + bias )
__global__ void k_agg(const float* __restrict__ H, const float* __restrict__ bias,
                      float* __restrict__ OUT, int do_relu) {
    int gid = blockIdx.x * blockDim.x + threadIdx.x;
    int node = gid >> 3;
    if (node >= NN) return;
    int l = (gid & 7) * 8;

    float di = g_dinv[node];
    float sw = di * di;
    const float* hn = H + (size_t)node * HID + l;
    float4 a0 = *(const float4*)(hn);
    float4 a1 = *(const float4*)(hn + 4);
    float4 b0 = *(const float4*)(bias + l);
    float4 b1v = *(const float4*)(bias + l + 4);
    a0.x = a0.x * sw + b0.x;  a0.y = a0.y * sw + b0.y;
    a0.z = a0.z * sw + b0.z;  a0.w = a0.w * sw + b0.w;
    a1.x = a1.x * sw + b1v.x; a1.y = a1.y * sw + b1v.y;
    a1.z = a1.z * sw + b1v.z; a1.w = a1.w * sw + b1v.w;

    int e1 = g_off[node + 1];
    for (int e = g_off[node]; e < e1; e++) {
        int s = g_csrc[e];
        float w = g_cnorm[e];
        const float* hs = H + (size_t)s * HID + l;
        float4 v0 = *(const float4*)(hs);
        float4 v1 = *(const float4*)(hs + 4);
        a0.x += v0.x * w; a0.y += v0.y * w; a0.z += v0.z * w; a0.w += v0.w * w;
        a1.x += v1.x * w; a1.y += v1.y * w; a1.z += v1.z * w; a1.w += v1.w * w;
    }
    if (do_relu) {
        a0.x = fmaxf(a0.x, 0.f); a0.y = fmaxf(a0.y, 0.f);
        a0.z = fmaxf(a0.z, 0.f); a0.w = fmaxf(a0.w, 0.f);
        a1.x = fmaxf(a1.x, 0.f); a1.y = fmaxf(a1.y, 0.f);
        a1.z = fmaxf(a1.z, 0.f); a1.w = fmaxf(a1.w, 0.f);
    }
    float* on = OUT + (size_t)node * HID + l;
    *(float4*)(on) = a0;
    *(float4*)(on + 4) = a1;
}

extern "C" void kernel_launch(void* const* d_in, const int* in_sizes, int n_in,
                              void* d_out, int out_size) {
    const float* x  = (const float*)d_in[0];
    const int*   ei = (const int*)d_in[1];   // [2, E] row-major: src then dst
    const float* W1 = (const float*)d_in[2];
    const float* b1 = (const float*)d_in[3];
    const float* W2 = (const float*)d_in[4];
    const float* b2 = (const float*)d_in[5];
    float* out = (float*)d_out;
    const int* src = ei;
    const int* dst = ei + EE;

    float *ph, *pact;
    cudaGetSymbolAddress((void**)&ph, g_h);
    cudaGetSymbolAddress((void**)&pact, g_act);

    // Graph structure (CSR by dst) — built fresh every call (deterministic work)
    k_zero<<<(NN + 255) / 256, 256>>>();
    k_hist<<<(EE + 255) / 256, 256>>>(dst);
    k_scan<<<1, 1024>>>();
    k_fill<<<(EE + 255) / 256, 256>>>(src, dst);

    // Layer 1
    k_gemm<<<(NN + 127) / 128, 128>>>(x, W1, ph, NN, 512);
    k_agg<<<(NN * 8 + 255) / 256, 256>>>(ph, b1, pact, 1);
    // Layer 2
    k_gemm<<<(NN + 127) / 128, 128>>>(pact, W2, ph, NN, HID);
    k_agg<<<(NN * 8 + 255) / 256, 256>>>(ph, b2, out, 0);
}

// round 2
// speedup vs baseline: 1.1874x; 1.1874x over previous
#include <cuda_runtime.h>

#define NN 50000
#define EE 800000
#define HID 64

// Scratch (allocation-free rule: __device__ globals)
__device__ float g_h[NN * HID];     // GEMM output (pre-aggregation features)
__device__ float g_act[NN * HID];   // layer-1 activations
__device__ int   g_cnt[NN];         // in-degree histogram (dst-based, excl. self-loop)
__device__ int   g_off[NN + 1];     // CSR row offsets
__device__ int   g_cur[NN];         // fill cursors (init = off)
__device__ float g_dinv[NN];        // rsqrt(deg) per node (deg includes self-loop)
__device__ int   g_csrc[EE];        // CSR: source node per edge (grouped by dst)
__device__ float g_cnorm[EE];       // CSR: dinv[src]*dinv[dst] per edge

// ---- packed f32x2 helpers (sm_103a) ----
__device__ __forceinline__ void fma2(unsigned long long& d,
                                     unsigned long long a,
                                     unsigned long long b) {
    asm("fma.rn.f32x2 %0, %1, %2, %0;" : "+l"(d) : "l"(a), "l"(b));
}
__device__ __forceinline__ unsigned long long splat2(float v) {
    unsigned long long r;
    asm("mov.b64 %0, {%1, %1};" : "=l"(r) : "r"(__float_as_uint(v)));
    return r;
}
__device__ __forceinline__ float2 unpack2(unsigned long long v) {
    float2 f;
    unsigned lo, hi;
    asm("mov.b64 {%0, %1}, %2;" : "=r"(lo), "=r"(hi) : "l"(v));
    f.x = __uint_as_float(lo);
    f.y = __uint_as_float(hi);
    return f;
}

__global__ void k_hist(const int* __restrict__ dst) {
    int e = blockIdx.x * blockDim.x + threadIdx.x;
    if (e < EE) atomicAdd(&g_cnt[dst[e]], 1);
}

// Single-block scan, smem-staged for coalesced global traffic.
__global__ void k_scan() {
    extern __shared__ int buf[];        // NN ints (200KB dynamic)
    __shared__ int sm[1024];
    int t = threadIdx.x;
    for (int i = t; i < NN; i += 1024) buf[i] = g_cnt[i];
    __syncthreads();
    const int C = (NN + 1023) / 1024;   // 49
    int start = t * C;
    int end = start + C;
    if (end > NN) end = NN;
    int sum = 0;
    for (int i = start; i < end; i++) sum += buf[i];
    sm[t] = sum;
    __syncthreads();
    for (int ofs = 1; ofs < 1024; ofs <<= 1) {
        int v = (t >= ofs) ? sm[t - ofs] : 0;
        __syncthreads();
        sm[t] += v;
        __syncthreads();
    }
    int base = sm[t] - sum;             // exclusive prefix
    for (int i = start; i < end; i++) {
        int c = buf[i];
        buf[i] = base;
        base += c;
        g_dinv[i] = rsqrtf((float)(c + 1));  // +1 self-loop => deg > 0 always
    }
    __syncthreads();
    for (int i = t; i < NN; i += 1024) {
        int o = buf[i];
        g_off[i] = o;
        g_cur[i] = o;
    }
    if (t == 0) g_off[NN] = EE;
}

__global__ void k_fill(const int* __restrict__ src, const int* __restrict__ dst) {
    int e = blockIdx.x * blockDim.x + threadIdx.x;
    if (e >= EE) return;
    int s = src[e], d = dst[e];
    int pos = atomicAdd(&g_cur[d], 1);   // cursor starts at off[d]
    g_csrc[pos] = s;
    g_cnorm[pos] = g_dinv[s] * g_dinv[d];
}

// fp32 GEMM with packed fma.rn.f32x2: OUT[n,64] = X[n,Kdim] @ W[Kdim,64]
// Block 128 threads; tile 128 rows x 64 cols; thread micro-tile 16 rows x 4 cols
// held as 8 row-pairs x 4 cols of packed f32x2 accumulators.
__global__ __launch_bounds__(128, 4) void k_gemm(
    const float* __restrict__ X, const float* __restrict__ W,
    float* __restrict__ OUT, int n, int Kdim) {
    __shared__ float Xs[32][138];   // transposed: Xs[k][row]; 138 => 2-way max STS conflict, 8B-aligned pairs
    __shared__ float Ws[32][HID];
    int tid = threadIdx.x;
    int tx = tid & 15;      // 16 col-groups of 4
    int ty = tid >> 4;      // 8 row-groups of 16
    int r0 = blockIdx.x * 128;
    int rb = ty * 16;

    unsigned long long acc[8][4];
#pragma unroll
    for (int p = 0; p < 8; p++)
#pragma unroll
        for (int c = 0; c < 4; c++) acc[p][c] = 0ull;  // bits 0 == {0.f,0.f}

    for (int k0 = 0; k0 < Kdim; k0 += 32) {
        // X tile: 128 rows x 32 k, stored transposed (coalesced float4 gmem loads)
#pragma unroll
        for (int j = 0; j < 8; j++) {
            int idx = tid + j * 128;
            int row = idx >> 3;
            int c4 = (idx & 7) * 4;
            float4 v = make_float4(0.f, 0.f, 0.f, 0.f);
            int gr = r0 + row;
            if (gr < n) v = *(const float4*)(X + (size_t)gr * Kdim + k0 + c4);
            Xs[c4][row] = v.x; Xs[c4 + 1][row] = v.y;
            Xs[c4 + 2][row] = v.z; Xs[c4 + 3][row] = v.w;
        }
        // W tile: 32 k x 64 cols
#pragma unroll
        for (int j = 0; j < 4; j++) {
            int idx = tid + j * 128;
            int row = idx >> 4;
            int c4 = (idx & 15) * 4;
            *(float4*)(&Ws[row][c4]) =
                *(const float4*)(W + (size_t)(k0 + row) * HID + c4);
        }
        __syncthreads();
#pragma unroll
        for (int kk = 0; kk < 32; kk++) {
            float4 wv = *(const float4*)(&Ws[kk][tx * 4]);
            unsigned long long w0 = splat2(wv.x);
            unsigned long long w1 = splat2(wv.y);
            unsigned long long w2 = splat2(wv.z);
            unsigned long long w3 = splat2(wv.w);
#pragma unroll
            for (int p = 0; p < 8; p++) {
                unsigned long long xp =
                    *(const unsigned long long*)(&Xs[kk][rb + 2 * p]);
                fma2(acc[p][0], xp, w0);
                fma2(acc[p][1], xp, w1);
                fma2(acc[p][2], xp, w2);
                fma2(acc[p][3], xp, w3);
            }
        }
        __syncthreads();
    }
#pragma unroll
    for (int p = 0; p < 8; p++) {
        int r = r0 + rb + 2 * p;
        float2 c0 = unpack2(acc[p][0]);
        float2 c1 = unpack2(acc[p][1]);
        float2 c2 = unpack2(acc[p][2]);
        float2 c3 = unpack2(acc[p][3]);
        if (r < n)
            *(float4*)(OUT + (size_t)r * HID + tx * 4) =
                make_float4(c0.x, c1.x, c2.x, c3.x);
        if (r + 1 < n)
            *(float4*)(OUT + (size_t)(r + 1) * HID + tx * 4) =
                make_float4(c0.y, c1.y, c2.y, c3.y);
    }
}

// Gather aggregation: 8 threads per node, each owns 8 of the 64 features.
// out[i] = [relu]( sum_{e: dst=i} H[src_e]*norm_e + dinv[i]^2*H[i] + bias )
__global__ void k_agg(const float* __restrict__ H, const float* __restrict__ bias,
                      float* __restrict__ OUT, int do_relu) {
    int gid = blockIdx.x * blockDim.x + threadIdx.x;
    int node = gid >> 3;
    if (node >= NN) return;
    int l = (gid & 7) * 8;

    float di = g_dinv[node];
    float sw = di * di;
    const float* hn = H + (size_t)node * HID + l;
    float4 a0 = *(const float4*)(hn);
    float4 a1 = *(const float4*)(hn + 4);
    float4 b0 = *(const float4*)(bias + l);
    float4 b1v = *(const float4*)(bias + l + 4);
    a0.x = a0.x * sw + b0.x;  a0.y = a0.y * sw + b0.y;
    a0.z = a0.z * sw + b0.z;  a0.w = a0.w * sw + b0.w;
    a1.x = a1.x * sw + b1v.x; a1.y = a1.y * sw + b1v.y;
    a1.z = a1.z * sw + b1v.z; a1.w = a1.w * sw + b1v.w;

    int e1 = g_off[node + 1];
    for (int e = g_off[node]; e < e1; e++) {
        int s = g_csrc[e];
        float w = g_cnorm[e];
        const float* hs = H + (size_t)s * HID + l;
        float4 v0 = *(const float4*)(hs);
        float4 v1 = *(const float4*)(hs + 4);
        a0.x += v0.x * w; a0.y += v0.y * w; a0.z += v0.z * w; a0.w += v0.w * w;
        a1.x += v1.x * w; a1.y += v1.y * w; a1.z += v1.z * w; a1.w += v1.w * w;
    }
    if (do_relu) {
        a0.x = fmaxf(a0.x, 0.f); a0.y = fmaxf(a0.y, 0.f);
        a0.z = fmaxf(a0.z, 0.f); a0.w = fmaxf(a0.w, 0.f);
        a1.x = fmaxf(a1.x, 0.f); a1.y = fmaxf(a1.y, 0.f);
        a1.z = fmaxf(a1.z, 0.f); a1.w = fmaxf(a1.w, 0.f);
    }
    float* on = OUT + (size_t)node * HID + l;
    *(float4*)(on) = a0;
    *(float4*)(on + 4) = a1;
}

extern "C" void kernel_launch(void* const* d_in, const int* in_sizes, int n_in,
                              void* d_out, int out_size) {
    const float* x  = (const float*)d_in[0];
    const int*   ei = (const int*)d_in[1];   // [2, E] row-major: src then dst
    const float* W1 = (const float*)d_in[2];
    const float* b1 = (const float*)d_in[3];
    const float* W2 = (const float*)d_in[4];
    const float* b2 = (const float*)d_in[5];
    float* out = (float*)d_out;
    const int* src = ei;
    const int* dst = ei + EE;

    float *ph, *pact;
    void* pcnt;
    cudaGetSymbolAddress((void**)&ph, g_h);
    cudaGetSymbolAddress((void**)&pact, g_act);
    cudaGetSymbolAddress(&pcnt, g_cnt);

    cudaFuncSetAttribute(k_scan, cudaFuncAttributeMaxDynamicSharedMemorySize,
                         NN * (int)sizeof(int));

    // Graph structure (CSR by dst) — built fresh every call (deterministic work)
    cudaMemsetAsync(pcnt, 0, NN * sizeof(int));
    k_hist<<<(EE + 255) / 256, 256>>>(dst);
    k_scan<<<1, 1024, NN * sizeof(int)>>>();
    k_fill<<<(EE + 255) / 256, 256>>>(src, dst);

    // Layer 1
    k_gemm<<<(NN + 127) / 128, 128>>>(x, W1, ph, NN, 512);
    k_agg<<<(NN * 8 + 255) / 256, 256>>>(ph, b1, pact, 1);
    // Layer 2
    k_gemm<<<(NN + 127) / 128, 128>>>(pact, W2, ph, NN, HID);
    k_agg<<<(NN * 8 + 255) / 256, 256>>>(ph, b2, out, 0);
}

// round 4
// speedup vs baseline: 1.1910x; 1.0030x over previous
#include <cuda_runtime.h>
#include <cstdint>

#define NN 50000
#define EE 800000
#define HID 64

// ---------------- scratch (__device__ globals; no allocs allowed) ----------
__device__ float g_h[NN * HID];
__device__ float g_act[NN * HID];
__device__ int   g_cnt[NN];
__device__ int   g_off[NN + 1];
__device__ int   g_cur[NN];
__device__ float g_dinv[NN];
__device__ int   g_csrc[EE];
__device__ float g_cnorm[EE];

// ---- packed f32x2 helpers (sm_103a; ptxas never auto-emits FFMA2) ----
__device__ __forceinline__ void fma2(unsigned long long& d,
                                     unsigned long long a,
                                     unsigned long long b) {
    asm("fma.rn.f32x2 %0, %1, %2, %0;" : "+l"(d) : "l"(a), "l"(b));
}
__device__ __forceinline__ unsigned long long splat2(float v) {
    unsigned long long r;
    asm("mov.b64 %0, {%1, %1};" : "=l"(r) : "r"(__float_as_uint(v)));
    return r;
}
__device__ __forceinline__ float2 unpack2(unsigned long long v) {
    float2 f;
    unsigned lo, hi;
    asm("mov.b64 {%0, %1}, %2;" : "=r"(lo), "=r"(hi) : "l"(v));
    f.x = __uint_as_float(lo);
    f.y = __uint_as_float(hi);
    return f;
}

// ---------------- CSR construction -----------------------------------------
__global__ void k_hist(const int* __restrict__ dst) {
    int e = blockIdx.x * blockDim.x + threadIdx.x;
    if (e < EE) atomicAdd(&g_cnt[dst[e]], 1);
}

__global__ void k_scan() {
    extern __shared__ int buf[];
    __shared__ int sm[1024];
    int t = threadIdx.x;
    for (int i = t; i < NN; i += 1024) buf[i] = g_cnt[i];
    __syncthreads();
    const int C = (NN + 1023) / 1024;
    int start = t * C, end = start + C;
    if (end > NN) end = NN;
    int sum = 0;
    for (int i = start; i < end; i++) sum += buf[i];
    sm[t] = sum;
    __syncthreads();
    for (int ofs = 1; ofs < 1024; ofs <<= 1) {
        int v = (t >= ofs) ? sm[t - ofs] : 0;
        __syncthreads();
        sm[t] += v;
        __syncthreads();
    }
    int base = sm[t] - sum;
    for (int i = start; i < end; i++) {
        int c = buf[i];
        buf[i] = base;
        base += c;
        g_dinv[i] = rsqrtf((float)(c + 1));
    }
    __syncthreads();
    for (int i = t; i < NN; i += 1024) {
        int o = buf[i];
        g_off[i] = o;
        g_cur[i] = o;
    }
    if (t == 0) g_off[NN] = EE;
}

__global__ void k_fill(const int* __restrict__ src, const int* __restrict__ dst) {
    int e = blockIdx.x * blockDim.x + threadIdx.x;
    if (e >= EE) return;
    int s = src[e], d = dst[e];
    int pos = atomicAdd(&g_cur[d], 1);
    g_csrc[pos] = s;
    g_cnorm[pos] = g_dinv[s] * g_dinv[d];
}

// ---------------- FFMA2 GEMM: OUT[n,64] = X[n,Kdim] @ W[Kdim,64] -----------
// Block 128 threads, tile 64 rows x 64 cols, K-chunks of 32.
// Micro-tile: 8 rows (4 packed row-pairs) x 4 cols per thread.
// Register-prefetch pipeline: next chunk's LDGs issue before the FFMA loop.
#define XS_STRIDE 66   // even (8B-aligned pairs), 264 mod 32 = 8 -> <=2-way STS conflict

__global__ __launch_bounds__(128, 5) void k_gemm(
    const float* __restrict__ X, const float* __restrict__ W,
    float* __restrict__ OUT, int n, int Kdim) {
    __shared__ float Xs[32][XS_STRIDE];   // transposed: Xs[k][row], rows 0..63
    __shared__ float Ws[32][HID];
    int tid = threadIdx.x;
    int tx = tid & 15;       // col group (4 cols)
    int ty = tid >> 4;       // row group (8 rows)
    int r0 = blockIdx.x * 64;
    int rb = ty * 8;

    // per-thread load coords
    int xrow = tid >> 3;           // 0..15 (+16 per j)
    int xc4 = (tid & 7) * 4;       // k offset within chunk
    int wrow = tid >> 4;           // 0..7 (+8 per j)
    int wc4 = (tid & 15) * 4;      // n offset

    unsigned long long acc[4][4];
#pragma unroll
    for (int p = 0; p < 4; p++)
#pragma unroll
        for (int c = 0; c < 4; c++) acc[p][c] = 0ull;

    float4 px[4], pw[4];
    int nch = Kdim >> 5;

    // prefetch chunk 0
#pragma unroll
    for (int j = 0; j < 4; j++) {
        int gr = r0 + xrow + j * 16;
        px[j] = (gr < n) ? *(const float4*)(X + (size_t)gr * Kdim + xc4)
                         : make_float4(0.f, 0.f, 0.f, 0.f);
        pw[j] = *(const float4*)(W + (size_t)(wrow + j * 8) * HID + wc4);
    }

    for (int ch = 0; ch < nch; ch++) {
        // stage current chunk into smem
#pragma unroll
        for (int j = 0; j < 4; j++) {
            int row = xrow + j * 16;
            Xs[xc4][row] = px[j].x;
            Xs[xc4 + 1][row] = px[j].y;
            Xs[xc4 + 2][row] = px[j].z;
            Xs[xc4 + 3][row] = px[j].w;
            *(float4*)(&Ws[wrow + j * 8][wc4]) = pw[j];
        }
        __syncthreads();

        // prefetch next chunk (overlaps with FFMA loop below)
        if (ch + 1 < nch) {
            int k0 = (ch + 1) << 5;
#pragma unroll
            for (int j = 0; j < 4; j++) {
                int gr = r0 + xrow + j * 16;
                px[j] = (gr < n)
                    ? *(const float4*)(X + (size_t)gr * Kdim + k0 + xc4)
                    : make_float4(0.f, 0.f, 0.f, 0.f);
                pw[j] = *(const float4*)(W + (size_t)(k0 + wrow + j * 8) * HID + wc4);
            }
        }

#pragma unroll
        for (int kk = 0; kk < 32; kk++) {
            float4 wv = *(const float4*)(&Ws[kk][tx * 4]);
            unsigned long long w0 = splat2(wv.x);
            unsigned long long w1 = splat2(wv.y);
            unsigned long long w2 = splat2(wv.z);
            unsigned long long w3 = splat2(wv.w);
#pragma unroll
            for (int p = 0; p < 4; p++) {
                unsigned long long xp =
                    *(const unsigned long long*)(&Xs[kk][rb + 2 * p]);
                fma2(acc[p][0], xp, w0);
                fma2(acc[p][1], xp, w1);
                fma2(acc[p][2], xp, w2);
                fma2(acc[p][3], xp, w3);
            }
        }
        __syncthreads();
    }

#pragma unroll
    for (int p = 0; p < 4; p++) {
        int r = r0 + rb + 2 * p;
        float2 c0 = unpack2(acc[p][0]);
        float2 c1 = unpack2(acc[p][1]);
        float2 c2 = unpack2(acc[p][2]);
        float2 c3 = unpack2(acc[p][3]);
        if (r < n)
            *(float4*)(OUT + (size_t)r * HID + tx * 4) =
                make_float4(c0.x, c1.x, c2.x, c3.x);
        if (r + 1 < n)
            *(float4*)(OUT + (size_t)(r + 1) * HID + tx * 4) =
                make_float4(c0.y, c1.y, c2.y, c3.y);
    }
}

// ---------------- gather aggregation ---------------------------------------
// out[i] = [relu]( sum_{e: dst=i} H[src_e]*norm_e + dinv[i]^2*H[i] + bias )
__global__ void k_agg(const float* __restrict__ H, const float* __restrict__ bias,
                      float* __restrict__ OUT, int do_relu) {
    int gid = blockIdx.x * blockDim.x + threadIdx.x;
    int node = gid >> 3;
    if (node >= NN) return;
    int l = (gid & 7) * 8;

    float di = g_dinv[node];
    float sw = di * di;
    const float* hn = H + (size_t)node * HID + l;
    float4 a0 = *(const float4*)(hn);
    float4 a1 = *(const float4*)(hn + 4);
    float4 b0 = *(const float4*)(bias + l);
    float4 b1v = *(const float4*)(bias + l + 4);
    a0.x = a0.x * sw + b0.x;  a0.y = a0.y * sw + b0.y;
    a0.z = a0.z * sw + b0.z;  a0.w = a0.w * sw + b0.w;
    a1.x = a1.x * sw + b1v.x; a1.y = a1.y * sw + b1v.y;
    a1.z = a1.z * sw + b1v.z; a1.w = a1.w * sw + b1v.w;

    int e1 = g_off[node + 1];
    for (int e = g_off[node]; e < e1; e++) {
        int s = g_csrc[e];
        float w = g_cnorm[e];
        const float* hs = H + (size_t)s * HID + l;
        float4 v0 = *(const float4*)(hs);
        float4 v1 = *(const float4*)(hs + 4);
        a0.x += v0.x * w; a0.y += v0.y * w; a0.z += v0.z * w; a0.w += v0.w * w;
        a1.x += v1.x * w; a1.y += v1.y * w; a1.z += v1.z * w; a1.w += v1.w * w;
    }
    if (do_relu) {
        a0.x = fmaxf(a0.x, 0.f); a0.y = fmaxf(a0.y, 0.f);
        a0.z = fmaxf(a0.z, 0.f); a0.w = fmaxf(a0.w, 0.f);
        a1.x = fmaxf(a1.x, 0.f); a1.y = fmaxf(a1.y, 0.f);
        a1.z = fmaxf(a1.z, 0.f); a1.w = fmaxf(a1.w, 0.f);
    }
    float* on = OUT + (size_t)node * HID + l;
    *(float4*)(on) = a0;
    *(float4*)(on + 4) = a1;
}

extern "C" void kernel_launch(void* const* d_in, const int* in_sizes, int n_in,
                              void* d_out, int out_size) {
    const float* x  = (const float*)d_in[0];
    const int*   ei = (const int*)d_in[1];   // [2, E]: src row then dst row
    const float* W1 = (const float*)d_in[2];
    const float* b1 = (const float*)d_in[3];
    const float* W2 = (const float*)d_in[4];
    const float* b2 = (const float*)d_in[5];
    float* out = (float*)d_out;
    const int* src = ei;
    const int* dst = ei + EE;

    float *ph, *pact;
    void* pcnt;
    cudaGetSymbolAddress((void**)&ph, g_h);
    cudaGetSymbolAddress((void**)&pact, g_act);
    cudaGetSymbolAddress(&pcnt, g_cnt);

    cudaFuncSetAttribute(k_scan, cudaFuncAttributeMaxDynamicSharedMemorySize,
                         NN * (int)sizeof(int));

    // Graph structure (CSR by dst) — rebuilt every call (deterministic work)
    cudaMemsetAsync(pcnt, 0, NN * sizeof(int));
    k_hist<<<(EE + 255) / 256, 256>>>(dst);
    k_scan<<<1, 1024, NN * sizeof(int)>>>();
    k_fill<<<(EE + 255) / 256, 256>>>(src, dst);

    // Layer 1
    k_gemm<<<(NN + 63) / 64, 128>>>(x, W1, ph, NN, 512);
    k_agg<<<(NN * 8 + 255) / 256, 256>>>(ph, b1, pact, 1);
    // Layer 2
    k_gemm<<<(NN + 63) / 64, 128>>>(pact, W2, ph, NN, HID);
    k_agg<<<(NN * 8 + 255) / 256, 256>>>(ph, b2, out, 0);
}

// round 5
// speedup vs baseline: 1.3987x; 1.1744x over previous
#include <cuda_runtime.h>
#include <cuda_bf16.h>
#include <cstdint>

#define NN 50000
#define EE 800000
#define HID 64

// ---------------- scratch (__device__ globals; no allocs allowed) ----------
__device__ float g_h[NN * HID];
__device__ float g_act[NN * HID];
__device__ int   g_cnt[NN];
__device__ int   g_off[NN + 1];
__device__ int   g_cur[NN];
__device__ float g_dinv[NN];
__device__ int   g_csrc[EE];
__device__ float g_cnorm[EE];
// Pre-transposed, bf16-split weights: Wt[n][k] (k contiguous)
__device__ uint16_t g_wt1h[64 * 512];
__device__ uint16_t g_wt1l[64 * 512];
__device__ uint16_t g_wt2h[64 * 64];
__device__ uint16_t g_wt2l[64 * 64];

// ---------------- helpers ---------------------------------------------------
// pack {bf16(b) (hi), bf16(a) (lo)}
__device__ __forceinline__ uint32_t cvt_bf16x2(float hi_elem, float lo_elem) {
    uint32_t r;
    asm("cvt.rn.bf16x2.f32 %0, %1, %2;" : "=r"(r) : "f"(hi_elem), "f"(lo_elem));
    return r;
}
// split a pair (x0, x1) -> packed hi {bf(x1),bf(x0)} and packed lo residuals
__device__ __forceinline__ void split_pair(float x0, float x1,
                                           uint32_t& h, uint32_t& l) {
    h = cvt_bf16x2(x1, x0);
    float h0 = __uint_as_float(h << 16);
    float h1 = __uint_as_float(h & 0xffff0000u);
    l = cvt_bf16x2(x1 - h1, x0 - h0);
}
__device__ __forceinline__ void mma_bf16(float& d0, float& d1, float& d2, float& d3,
                                         uint32_t a0, uint32_t a1, uint32_t a2, uint32_t a3,
                                         uint32_t b0, uint32_t b1) {
    asm volatile("mma.sync.aligned.m16n8k16.row.col.f32.bf16.bf16.f32 "
                 "{%0,%1,%2,%3}, {%4,%5,%6,%7}, {%8,%9}, {%0,%1,%2,%3};"
                 : "+f"(d0), "+f"(d1), "+f"(d2), "+f"(d3)
                 : "r"(a0), "r"(a1), "r"(a2), "r"(a3), "r"(b0), "r"(b1));
}

// ---------------- CSR construction -----------------------------------------
__global__ void k_hist(const int* __restrict__ dst) {
    int e = blockIdx.x * blockDim.x + threadIdx.x;
    if (e < EE) atomicAdd(&g_cnt[dst[e]], 1);
}

__global__ void k_scan() {
    extern __shared__ int buf[];
    __shared__ int sm[1024];
    int t = threadIdx.x;
    for (int i = t; i < NN; i += 1024) buf[i] = g_cnt[i];
    __syncthreads();
    const int C = (NN + 1023) / 1024;
    int start = t * C, end = start + C;
    if (end > NN) end = NN;
    int sum = 0;
    for (int i = start; i < end; i++) sum += buf[i];
    sm[t] = sum;
    __syncthreads();
    for (int ofs = 1; ofs < 1024; ofs <<= 1) {
        int v = (t >= ofs) ? sm[t - ofs] : 0;
        __syncthreads();
        sm[t] += v;
        __syncthreads();
    }
    int base = sm[t] - sum;
    for (int i = start; i < end; i++) {
        int c = buf[i];
        buf[i] = base;
        base += c;
        g_dinv[i] = rsqrtf((float)(c + 1));
    }
    __syncthreads();
    for (int i = t; i < NN; i += 1024) {
        int o = buf[i];
        g_off[i] = o;
        g_cur[i] = o;
    }
    if (t == 0) g_off[NN] = EE;
}

__global__ void k_fill(const int* __restrict__ src, const int* __restrict__ dst) {
    int e = blockIdx.x * blockDim.x + threadIdx.x;
    if (e >= EE) return;
    int s = src[e], d = dst[e];
    int pos = atomicAdd(&g_cur[d], 1);
    g_csrc[pos] = s;
    g_cnorm[pos] = g_dinv[s] * g_dinv[d];
}

// ---------------- weight prep: transpose + bf16 hi/lo split -----------------
__global__ void k_prep(const float* __restrict__ W1, const float* __restrict__ W2) {
    int idx = blockIdx.x * blockDim.x + threadIdx.x;
    int total1 = 64 * 512;
    if (idx < total1) {
        int n = idx >> 9, k = idx & 511;
        float v = W1[k * 64 + n];
        uint16_t hs = __bfloat16_as_ushort(__float2bfloat16(v));
        float hf = __uint_as_float((uint32_t)hs << 16);
        uint16_t ls = __bfloat16_as_ushort(__float2bfloat16(v - hf));
        g_wt1h[idx] = hs;
        g_wt1l[idx] = ls;
    }
    if (idx < 64 * 64) {
        int n = idx >> 6, k = idx & 63;
        float v = W2[k * 64 + n];
        uint16_t hs = __bfloat16_as_ushort(__float2bfloat16(v));
        float hf = __uint_as_float((uint32_t)hs << 16);
        uint16_t ls = __bfloat16_as_ushort(__float2bfloat16(v - hf));
        g_wt2h[idx] = hs;
        g_wt2l[idx] = ls;
    }
}

// ---------------- HMMA bf16-split GEMM: OUT[n,64] = X[n,Kdim] @ W[Kdim,64] --
// Block 128 thr (4 warps), tile 64 rows x 64 cols, K-chunks of 32.
// Warp w: rows [16w, 16w+16), all 64 cols (8 n-tiles of m16n8k16).
// 3 products per tile: Ah*Bh + Ah*Bl + Al*Bh (fp32 accum).
#define XST 40   // smem row stride (bf16 units): (20*row + k/2) % 32 conflict-free

__global__ __launch_bounds__(128, 5) void k_gemm(
    const float* __restrict__ X,
    const uint16_t* __restrict__ Wth, const uint16_t* __restrict__ Wtl,
    float* __restrict__ OUT, int n, int Kdim) {
    __shared__ uint16_t Xh[64 * XST], Xl[64 * XST];
    __shared__ uint16_t Wh[64 * XST], Wl[64 * XST];
    int tid = threadIdx.x;
    int wid = tid >> 5;
    int lane = tid & 31;
    int gid = lane >> 2;     // 0..7
    int q = lane & 3;        // 0..3
    int r0 = blockIdx.x * 64;
    int rb = wid * 16;

    // staging coords
    int xrow = tid >> 3;          // 0..15  (X: 512 float4 per chunk, 4 iters)
    int xkg = (tid & 7) * 4;      // k offset (float4)
    int wn = tid >> 4;            // 0..7   (W: 1024 uint32 per chunk, 8 iters)
    int wkg = tid & 15;           // uint32 index within 32-k row

    const uint32_t* wh32 = (const uint32_t*)Wth;
    const uint32_t* wl32 = (const uint32_t*)Wtl;
    int wstride = Kdim >> 1;      // uint32 per Wt row

    float acc[8][4];
#pragma unroll
    for (int t = 0; t < 8; t++)
#pragma unroll
        for (int c = 0; c < 4; c++) acc[t][c] = 0.f;

    int nch = Kdim >> 5;
    float4 px[4];
    uint32_t pwh[8], pwl[8];

    // prefetch chunk 0
#pragma unroll
    for (int j = 0; j < 4; j++) {
        int gr = r0 + xrow + j * 16;
        px[j] = (gr < n) ? *(const float4*)(X + (size_t)gr * Kdim + xkg)
                         : make_float4(0.f, 0.f, 0.f, 0.f);
    }
#pragma unroll
    for (int j = 0; j < 8; j++) {
        int nn = wn + j * 8;
        pwh[j] = wh32[nn * wstride + wkg];
        pwl[j] = wl32[nn * wstride + wkg];
    }

    for (int ch = 0; ch < nch; ch++) {
        // stage chunk into smem (X: fp32 -> bf16 hi/lo split)
#pragma unroll
        for (int j = 0; j < 4; j++) {
            int row = xrow + j * 16;
            uint32_t h01, l01, h23, l23;
            split_pair(px[j].x, px[j].y, h01, l01);
            split_pair(px[j].z, px[j].w, h23, l23);
            uint32_t* dh = (uint32_t*)&Xh[row * XST + xkg];
            uint32_t* dl = (uint32_t*)&Xl[row * XST + xkg];
            dh[0] = h01; dh[1] = h23;
            dl[0] = l01; dl[1] = l23;
        }
#pragma unroll
        for (int j = 0; j < 8; j++) {
            int nn = wn + j * 8;
            *(uint32_t*)&Wh[nn * XST + wkg * 2] = pwh[j];
            *(uint32_t*)&Wl[nn * XST + wkg * 2] = pwl[j];
        }
        __syncthreads();

        // prefetch next chunk (overlaps MMA below)
        if (ch + 1 < nch) {
            int k0 = (ch + 1) << 5;
#pragma unroll
            for (int j = 0; j < 4; j++) {
                int gr = r0 + xrow + j * 16;
                px[j] = (gr < n)
                    ? *(const float4*)(X + (size_t)gr * Kdim + k0 + xkg)
                    : make_float4(0.f, 0.f, 0.f, 0.f);
            }
#pragma unroll
            for (int j = 0; j < 8; j++) {
                int nn = wn + j * 8;
                pwh[j] = wh32[nn * wstride + (k0 >> 1) + wkg];
                pwl[j] = wl32[nn * wstride + (k0 >> 1) + wkg];
            }
        }

        // 2 k-steps of 16 per chunk
#pragma unroll
        for (int s = 0; s < 2; s++) {
            int kb = s * 16 + 2 * q;
            // A fragments (hi & lo)
            uint32_t ah0 = *(const uint32_t*)&Xh[(rb + gid) * XST + kb];
            uint32_t ah1 = *(const uint32_t*)&Xh[(rb + gid + 8) * XST + kb];
            uint32_t ah2 = *(const uint32_t*)&Xh[(rb + gid) * XST + kb + 8];
            uint32_t ah3 = *(const uint32_t*)&Xh[(rb + gid + 8) * XST + kb + 8];
            uint32_t al0 = *(const uint32_t*)&Xl[(rb + gid) * XST + kb];
            uint32_t al1 = *(const uint32_t*)&Xl[(rb + gid + 8) * XST + kb];
            uint32_t al2 = *(const uint32_t*)&Xl[(rb + gid) * XST + kb + 8];
            uint32_t al3 = *(const uint32_t*)&Xl[(rb + gid + 8) * XST + kb + 8];
#pragma unroll
            for (int nt = 0; nt < 8; nt++) {
                int ncol = nt * 8 + gid;
                uint32_t bh0 = *(const uint32_t*)&Wh[ncol * XST + kb];
                uint32_t bh1 = *(const uint32_t*)&Wh[ncol * XST + kb + 8];
                uint32_t bl0 = *(const uint32_t*)&Wl[ncol * XST + kb];
                uint32_t bl1 = *(const uint32_t*)&Wl[ncol * XST + kb + 8];
                mma_bf16(acc[nt][0], acc[nt][1], acc[nt][2], acc[nt][3],
                         ah0, ah1, ah2, ah3, bh0, bh1);
                mma_bf16(acc[nt][0], acc[nt][1], acc[nt][2], acc[nt][3],
                         ah0, ah1, ah2, ah3, bl0, bl1);
                mma_bf16(acc[nt][0], acc[nt][1], acc[nt][2], acc[nt][3],
                         al0, al1, al2, al3, bh0, bh1);
            }
        }
        __syncthreads();
    }

    // epilogue: c0=(row, col), c1=(row, col+1), c2=(row+8, col), c3=(row+8, col+1)
    int gr0 = r0 + rb + gid;
    int gr1 = gr0 + 8;
#pragma unroll
    for (int nt = 0; nt < 8; nt++) {
        int col = nt * 8 + 2 * q;
        if (gr0 < n)
            *(float2*)(OUT + (size_t)gr0 * HID + col) =
                make_float2(acc[nt][0], acc[nt][1]);
        if (gr1 < n)
            *(float2*)(OUT + (size_t)gr1 * HID + col) =
                make_float2(acc[nt][2], acc[nt][3]);
    }
}

// ---------------- gather aggregation ---------------------------------------
__global__ void k_agg(const float* __restrict__ H, const float* __restrict__ bias,
                      float* __restrict__ OUT, int do_relu) {
    int gid = blockIdx.x * blockDim.x + threadIdx.x;
    int node = gid >> 3;
    if (node >= NN) return;
    int l = (gid & 7) * 8;

    float di = g_dinv[node];
    float sw = di * di;
    const float* hn = H + (size_t)node * HID + l;
    float4 a0 = *(const float4*)(hn);
    float4 a1 = *(const float4*)(hn + 4);
    float4 b0 = *(const float4*)(bias + l);
    float4 b1v = *(const float4*)(bias + l + 4);
    a0.x = a0.x * sw + b0.x;  a0.y = a0.y * sw + b0.y;
    a0.z = a0.z * sw + b0.z;  a0.w = a0.w * sw + b0.w;
    a1.x = a1.x * sw + b1v.x; a1.y = a1.y * sw + b1v.y;
    a1.z = a1.z * sw + b1v.z; a1.w = a1.w * sw + b1v.w;

    int e1 = g_off[node + 1];
    for (int e = g_off[node]; e < e1; e++) {
        int s = g_csrc[e];
        float w = g_cnorm[e];
        const float* hs = H + (size_t)s * HID + l;
        float4 v0 = *(const float4*)(hs);
        float4 v1 = *(const float4*)(hs + 4);
        a0.x += v0.x * w; a0.y += v0.y * w; a0.z += v0.z * w; a0.w += v0.w * w;
        a1.x += v1.x * w; a1.y += v1.y * w; a1.z += v1.z * w; a1.w += v1.w * w;
    }
    if (do_relu) {
        a0.x = fmaxf(a0.x, 0.f); a0.y = fmaxf(a0.y, 0.f);
        a0.z = fmaxf(a0.z, 0.f); a0.w = fmaxf(a0.w, 0.f);
        a1.x = fmaxf(a1.x, 0.f); a1.y = fmaxf(a1.y, 0.f);
        a1.z = fmaxf(a1.z, 0.f); a1.w = fmaxf(a1.w, 0.f);
    }
    float* on = OUT + (size_t)node * HID + l;
    *(float4*)(on) = a0;
    *(float4*)(on + 4) = a1;
}

extern "C" void kernel_launch(void* const* d_in, const int* in_sizes, int n_in,
                              void* d_out, int out_size) {
    const float* x  = (const float*)d_in[0];
    const int*   ei = (const int*)d_in[1];   // [2, E]: src row then dst row
    const float* W1 = (const float*)d_in[2];
    const float* b1 = (const float*)d_in[3];
    const float* W2 = (const float*)d_in[4];
    const float* b2 = (const float*)d_in[5];
    float* out = (float*)d_out;
    const int* src = ei;
    const int* dst = ei + EE;

    float *ph, *pact;
    void* pcnt;
    uint16_t *w1h, *w1l, *w2h, *w2l;
    cudaGetSymbolAddress((void**)&ph, g_h);
    cudaGetSymbolAddress((void**)&pact, g_act);
    cudaGetSymbolAddress(&pcnt, g_cnt);
    cudaGetSymbolAddress((void**)&w1h, g_wt1h);
    cudaGetSymbolAddress((void**)&w1l, g_wt1l);
    cudaGetSymbolAddress((void**)&w2h, g_wt2h);
    cudaGetSymbolAddress((void**)&w2l, g_wt2l);

    cudaFuncSetAttribute(k_scan, cudaFuncAttributeMaxDynamicSharedMemorySize,
                         NN * (int)sizeof(int));

    // Graph structure (CSR by dst) + weight prep
    cudaMemsetAsync(pcnt, 0, NN * sizeof(int));
    k_hist<<<(EE + 255) / 256, 256>>>(dst);
    k_prep<<<(64 * 512 + 255) / 256, 256>>>(W1, W2);
    k_scan<<<1, 1024, NN * sizeof(int)>>>();
    k_fill<<<(EE + 255) / 256, 256>>>(src, dst);

    // Layer 1
    k_gemm<<<(NN + 63) / 64, 128>>>(x, w1h, w1l, ph, NN, 512);
    k_agg<<<(NN * 8 + 255) / 256, 256>>>(ph, b1, pact, 1);
    // Layer 2
    k_gemm<<<(NN + 63) / 64, 128>>>(pact, w2h, w2l, ph, NN, HID);
    k_agg<<<(NN * 8 + 255) / 256, 256>>>(ph, b2, out, 0);
}